// round 3
// baseline (speedup 1.0000x reference)
#include <cuda_runtime.h>

#define N_PROP 65536
#define N_TGT  128
#define KTOP   8
#define NPB    32   // proposals per block in the score kernel

// Scratch (static __device__ — no allocations allowed)
__device__ float g_scoresT[(size_t)N_TGT * N_PROP];   // [T][N] logit keys
__device__ float g_top_val[N_TGT * KTOP];
__device__ int   g_top_idx[N_TGT * KTOP];

// ---------------------------------------------------------------------------
// Kernel 1: MLP scoring. blockDim=128 (thread = target t), each block covers
// NPB proposals; 2 proposals per thread per iteration amortize the broadcast
// weight LDS over 2x the FMAs.
// key = logit if logit >= 0 else -1.0 (sentinel reproduces the zeros-tie of
// the thresholded reference; sigmoid is monotone so ranking by logit is exact)
// ---------------------------------------------------------------------------
__global__ __launch_bounds__(128) void score_kernel(
    const float* __restrict__ th, const float* __restrict__ xy,
    const float* __restrict__ di, const float* __restrict__ po,
    const float* __restrict__ ne, const float* __restrict__ io,
    const float* __restrict__ W1, const float* __restrict__ b1,
    const float* __restrict__ W2, const float* __restrict__ b2,
    const float* __restrict__ W3, const float* __restrict__ b3)
{
    __shared__ __align__(16) float sW1[64 * 8];   // [i][k0..k5, b1_i, pad]
    __shared__ __align__(16) float sW2[64 * 32];  // row-major [i][j]
    __shared__ __align__(16) float sW3[32];
    __shared__ float sB2[32];
    __shared__ float sB3;

    const int tid = threadIdx.x;

    for (int x = tid; x < 64 * 8; x += 128) {
        int i = x >> 3, k = x & 7;
        float v = 0.0f;
        if (k < 6)       v = W1[k * 64 + i];
        else if (k == 6) v = b1[i];
        sW1[x] = v;
    }
    for (int x = tid; x < 64 * 32; x += 128) sW2[x] = W2[x];
    if (tid < 32) { sW3[tid] = W3[tid]; sB2[tid] = b2[tid]; }
    if (tid == 0) sB3 = b3[0];
    __syncthreads();

    const int t  = tid;            // target index 0..127
    const int n0 = blockIdx.x * NPB;

    for (int nn = 0; nn < NPB; nn += 2) {
        const int na = n0 + nn;
        const int oa = na * N_TGT + t;
        const int ob = oa + N_TGT;

        float fa[6], fb[6];
        fa[0] = 1.0f - fminf(th[oa], 180.0f) * (1.0f / 180.0f);
        fb[0] = 1.0f - fminf(th[ob], 180.0f) * (1.0f / 180.0f);
        fa[1] = 1.0f - fminf(xy[oa], 800.0f) * (1.0f / 800.0f);
        fb[1] = 1.0f - fminf(xy[ob], 800.0f) * (1.0f / 800.0f);
        fa[2] = 1.0f - fminf(di[oa], 800.0f) * (1.0f / 800.0f);
        fb[2] = 1.0f - fminf(di[ob], 800.0f) * (1.0f / 800.0f);
        fa[3] = po[oa]; fb[3] = po[ob];
        fa[4] = ne[oa]; fb[4] = ne[ob];
        fa[5] = io[oa]; fb[5] = io[ob];

        float h2a[32], h2b[32];
        #pragma unroll
        for (int j = 0; j < 32; j++) { h2a[j] = sB2[j]; h2b[j] = sB2[j]; }

        #pragma unroll 4
        for (int i = 0; i < 64; i++) {
            const float4 w0 = ((const float4*)sW1)[i * 2 + 0];
            const float4 w1 = ((const float4*)sW1)[i * 2 + 1];

            float ha = w1.z;  // b1[i]
            ha = fmaf(fa[0], w0.x, ha); ha = fmaf(fa[1], w0.y, ha);
            ha = fmaf(fa[2], w0.z, ha); ha = fmaf(fa[3], w0.w, ha);
            ha = fmaf(fa[4], w1.x, ha); ha = fmaf(fa[5], w1.y, ha);
            float hb = w1.z;
            hb = fmaf(fb[0], w0.x, hb); hb = fmaf(fb[1], w0.y, hb);
            hb = fmaf(fb[2], w0.z, hb); hb = fmaf(fb[3], w0.w, hb);
            hb = fmaf(fb[4], w1.x, hb); hb = fmaf(fb[5], w1.y, hb);
            ha = fmaxf(ha, 0.0f);
            hb = fmaxf(hb, 0.0f);

            #pragma unroll
            for (int j = 0; j < 8; j++) {
                const float4 w = ((const float4*)sW2)[i * 8 + j];
                h2a[4 * j + 0] = fmaf(ha, w.x, h2a[4 * j + 0]);
                h2a[4 * j + 1] = fmaf(ha, w.y, h2a[4 * j + 1]);
                h2a[4 * j + 2] = fmaf(ha, w.z, h2a[4 * j + 2]);
                h2a[4 * j + 3] = fmaf(ha, w.w, h2a[4 * j + 3]);
                h2b[4 * j + 0] = fmaf(hb, w.x, h2b[4 * j + 0]);
                h2b[4 * j + 1] = fmaf(hb, w.y, h2b[4 * j + 1]);
                h2b[4 * j + 2] = fmaf(hb, w.z, h2b[4 * j + 2]);
                h2b[4 * j + 3] = fmaf(hb, w.w, h2b[4 * j + 3]);
            }
        }

        float acca = sB3, accb = sB3;
        #pragma unroll
        for (int j = 0; j < 32; j++) {
            const float w = sW3[j];
            acca = fmaf(fmaxf(h2a[j], 0.0f), w, acca);
            accb = fmaf(fmaxf(h2b[j], 0.0f), w, accb);
        }

        g_scoresT[(size_t)t * N_PROP + na]     = (acca >= 0.0f) ? acca : -1.0f;
        g_scoresT[(size_t)t * N_PROP + na + 1] = (accb >= 0.0f) ? accb : -1.0f;
    }
}

// ---------------------------------------------------------------------------
// Kernel 2: per-target top-8, ties broken by lowest index (lax.top_k rule).
// ---------------------------------------------------------------------------
__global__ __launch_bounds__(256) void topk_kernel()
{
    __shared__ float sval[256 * KTOP];
    __shared__ int   sidx[256 * KTOP];

    const int t   = blockIdx.x;
    const int tid = threadIdx.x;
    const float* __restrict__ col = g_scoresT + (size_t)t * N_PROP;

    float val[KTOP];
    int   idx[KTOP];
    #pragma unroll
    for (int k = 0; k < KTOP; k++) { val[k] = -3.4e38f; idx[k] = 0x7fffffff; }

    for (int n = tid; n < N_PROP; n += 256) {
        const float v = col[n];
        if (v > val[KTOP - 1]) {
            val[KTOP - 1] = v; idx[KTOP - 1] = n;
            #pragma unroll
            for (int p = KTOP - 1; p > 0; p--) {
                if (val[p] > val[p - 1]) {
                    float tv = val[p]; val[p] = val[p - 1]; val[p - 1] = tv;
                    int   ti = idx[p]; idx[p] = idx[p - 1]; idx[p - 1] = ti;
                }
            }
        }
    }

    #pragma unroll
    for (int k = 0; k < KTOP; k++) { sval[tid * KTOP + k] = val[k]; sidx[tid * KTOP + k] = idx[k]; }
    __syncthreads();

    for (int s = 128; s > 0; s >>= 1) {
        float mv[KTOP]; int mi[KTOP];
        if (tid < s) {
            const float* av = &sval[tid * KTOP];
            const int*   ai = &sidx[tid * KTOP];
            const float* bv = &sval[(tid + s) * KTOP];
            const int*   bi = &sidx[(tid + s) * KTOP];
            int i = 0, j = 0;
            #pragma unroll
            for (int k = 0; k < KTOP; k++) {
                const float va = av[i], vb = bv[j];
                const int   ia = ai[i], ib = bi[j];
                const bool take_a = (va > vb) || (va == vb && ia < ib);
                if (take_a) { mv[k] = va; mi[k] = ia; i++; }
                else        { mv[k] = vb; mi[k] = ib; j++; }
            }
            #pragma unroll
            for (int k = 0; k < KTOP; k++) { sval[tid * KTOP + k] = mv[k]; sidx[tid * KTOP + k] = mi[k]; }
        }
        __syncthreads();
    }

    if (tid == 0) {
        #pragma unroll
        for (int k = 0; k < KTOP; k++) {
            g_top_val[t * KTOP + k] = sval[k];
            g_top_idx[t * KTOP + k] = sidx[k];
        }
    }
}

// ---------------------------------------------------------------------------
// Kernel 3: stable descending rank of targets[:,1], scatter output as FLOAT32.
// out = [rows(1024) | cols(1024) | valid(1024)] as float32.
// ---------------------------------------------------------------------------
__global__ __launch_bounds__(N_TGT) void assemble_kernel(
    const float* __restrict__ targets, float* __restrict__ out)
{
    __shared__ float key[N_TGT];
    const int t = threadIdx.x;
    key[t] = targets[t * 4 + 1];
    __syncthreads();

    const float kt = key[t];
    int r = 0;
    #pragma unroll 8
    for (int j = 0; j < N_TGT; j++) {
        const float kj = key[j];
        r += (kj > kt) || (kj == kt && j < t);   // stable descending
    }

    #pragma unroll
    for (int k = 0; k < KTOP; k++) {
        const int src = t * KTOP + k;
        const int dst = r * KTOP + k;
        out[dst]        = (float)g_top_idx[src];                 // rows
        out[1024 + dst] = (float)t;                              // cols
        out[2048 + dst] = (g_top_val[src] >= 0.0f) ? 1.0f : 0.0f; // valid
    }
}

// ---------------------------------------------------------------------------
extern "C" void kernel_launch(void* const* d_in, const int* in_sizes, int n_in,
                              void* d_out, int out_size)
{
    const float *th, *xy, *di, *po, *ne, *io, *tg, *W1, *b1, *W2, *b2, *W3, *b3;

    if (n_in >= 13 && in_sizes[0] == 6 * 64) {
        // Alphabetical metadata order: W1,W2,W3,b1,b2,b3,dist,iou,neg,pos,xys,targets,theta
        W1 = (const float*)d_in[0];  W2 = (const float*)d_in[1];
        W3 = (const float*)d_in[2];  b1 = (const float*)d_in[3];
        b2 = (const float*)d_in[4];  b3 = (const float*)d_in[5];
        di = (const float*)d_in[6];  io = (const float*)d_in[7];
        ne = (const float*)d_in[8];  po = (const float*)d_in[9];
        xy = (const float*)d_in[10]; tg = (const float*)d_in[11];
        th = (const float*)d_in[12];
    } else {
        // Insertion (dict) order
        th = (const float*)d_in[0];  xy = (const float*)d_in[1];
        di = (const float*)d_in[2];  po = (const float*)d_in[3];
        ne = (const float*)d_in[4];  io = (const float*)d_in[5];
        tg = (const float*)d_in[6];  W1 = (const float*)d_in[7];
        b1 = (const float*)d_in[8];  W2 = (const float*)d_in[9];
        b2 = (const float*)d_in[10]; W3 = (const float*)d_in[11];
        b3 = (const float*)d_in[12];
    }

    score_kernel<<<N_PROP / NPB, 128>>>(th, xy, di, po, ne, io,
                                        W1, b1, W2, b2, W3, b3);
    topk_kernel<<<N_TGT, 256>>>();
    assemble_kernel<<<1, N_TGT>>>(tg, (float*)d_out);
}